// round 17
// baseline (speedup 1.0000x reference)
#include <cuda_runtime.h>
#include <cuda_bf16.h>
#include <cuda_fp16.h>
#include <math.h>

// Problem constants
#define Bq  4
#define Hh  64
#define Ww  64
#define Cc  128
#define NHh 4
#define Kk  7
#define HDd 32
#define MLPD 512
#define NTOK (Bq*Hh*Ww)   // 16384

typedef __nv_bfloat16  bf16;
typedef __nv_bfloat162 bf162;

// Scratch (device globals)
__device__ __align__(16) bf16  g_qn    [NTOK*Cc];
__device__ __align__(16) bf16  g_kvn   [NTOK*Cc];
__device__ __align__(16) bf16  g_q     [NTOK*Cc];
__device__ __align__(16) bf16  g_kv    [NTOK*2*Cc];   // K half bf16, V half f16
__device__ __align__(16) bf16  g_attn  [NTOK*Cc];

// bf16 weights (converted once per launch)
__device__ __align__(16) bf16  g_wq [Cc*Cc];
__device__ __align__(16) bf16  g_wkv[Cc*2*Cc];
__device__ __align__(16) bf16  g_wp [Cc*Cc];
__device__ __align__(16) bf16  g_w1 [Cc*MLPD];
__device__ __align__(16) bf16  g_w2 [MLPD*Cc];

__device__ __forceinline__ unsigned s2u(const void* p) {
    return (unsigned)__cvta_generic_to_shared(p);
}

#define CP_ASYNC16(dst, src) \
    asm volatile("cp.async.ca.shared.global [%0], [%1], 16;" :: "r"(dst), "l"(src))

#define LOG2E 1.4426950408889634f

// ---------------------------------------------------------------------------
// Prep kernel: blocks [0,4096) = dual LayerNorm; blocks [4096,4288) = weight cvt
// ---------------------------------------------------------------------------
__global__ void prep_kernel(const float* __restrict__ in1, const float* __restrict__ gg1,
                            const float* __restrict__ bb1, bf16* __restrict__ out1,
                            const float* __restrict__ in2, const float* __restrict__ gg2,
                            const float* __restrict__ bb2, bf16* __restrict__ out2,
                            const float* __restrict__ Wq, const float* __restrict__ Wkv,
                            const float* __restrict__ Wp, const float* __restrict__ W1,
                            const float* __restrict__ W2)
{
    if (blockIdx.x >= 4096) {
        int i = (blockIdx.x - 4096) * 256 + threadIdx.x;   // 0..49151
        const float* src; bf16* dst; int off;
        if      (i < 4096)  { src = Wq;  dst = g_wq;  off = i; }
        else if (i < 12288) { src = Wkv; dst = g_wkv; off = i - 4096; }
        else if (i < 16384) { src = Wp;  dst = g_wp;  off = i - 12288; }
        else if (i < 32768) { src = W1;  dst = g_w1;  off = i - 16384; }
        else                { src = W2;  dst = g_w2;  off = i - 32768; }
        float4 v = ((const float4*)src)[off];
        bf162 lo = __float22bfloat162_rn(make_float2(v.x, v.y));
        bf162 hi = __float22bfloat162_rn(make_float2(v.z, v.w));
        uint2 pk; pk.x = *(unsigned*)&lo; pk.y = *(unsigned*)&hi;
        ((uint2*)dst)[off] = pk;
        return;
    }

    int w    = (blockIdx.x * blockDim.x + threadIdx.x) >> 5;
    int lane = threadIdx.x & 31;
    const float* in; const float* g; const float* b; bf16* out; int tok;
    if (w < NTOK) { in = in1; g = gg1; b = bb1; out = out1; tok = w; }
    else          { in = in2; g = gg2; b = bb2; out = out2; tok = w - NTOK; }

    const float4 v = *(const float4*)&in[(size_t)tok*Cc + lane*4];
    float s  = v.x + v.y + v.z + v.w;
    float sq = v.x*v.x + v.y*v.y + v.z*v.z + v.w*v.w;
    #pragma unroll
    for (int off = 16; off; off >>= 1) {
        s  += __shfl_xor_sync(0xffffffff, s,  off);
        sq += __shfl_xor_sync(0xffffffff, sq, off);
    }
    float mean = s * (1.0f/Cc);
    float var  = sq * (1.0f/Cc) - mean*mean;
    float inv  = rsqrtf(var + 1e-5f);

    const float4 gv = *(const float4*)&g[lane*4];
    const float4 bv = *(const float4*)&b[lane*4];
    bf162 o0 = __float22bfloat162_rn(make_float2((v.x-mean)*inv*gv.x + bv.x,
                                                 (v.y-mean)*inv*gv.y + bv.y));
    bf162 o1 = __float22bfloat162_rn(make_float2((v.z-mean)*inv*gv.z + bv.z,
                                                 (v.w-mean)*inv*gv.w + bv.w));
    uint2 pk; pk.x = *(unsigned*)&o0; pk.y = *(unsigned*)&o1;
    *(uint2*)&out[(size_t)tok*Cc + lane*4] = pk;
}

// ---------------------------------------------------------------------------
// MMA tile helper: one BK=32 slab (trans-B, [k][n] layout), bf16.
// ---------------------------------------------------------------------------
__device__ __forceinline__ void gemm_tile(
    unsigned aB, unsigned bB, int m_base, int n_base, int lane,
    float acc[8][4], int apitch, int bpitch)
{
    const int a_row_sel = lane & 15;
    const int a_k_sel   = (lane >> 4) << 3;
    const int b_k_sel   = (lane & 7) + (((lane >> 3) & 1) << 3);
    const int b_n_sel   = (lane >> 4) << 3;
    #pragma unroll
    for (int kk = 0; kk < 32; kk += 16) {
        unsigned af[4], bf[8][2];
        {
            unsigned addr = aB + ((m_base + a_row_sel)*apitch + kk + a_k_sel)*2;
            asm volatile("ldmatrix.sync.aligned.m8n8.x4.shared.b16 {%0,%1,%2,%3}, [%4];"
                : "=r"(af[0]), "=r"(af[1]), "=r"(af[2]), "=r"(af[3]) : "r"(addr));
        }
        #pragma unroll
        for (int np = 0; np < 4; np++) {
            unsigned r0, r1, r2, r3;
            unsigned addr = bB + ((kk + b_k_sel)*bpitch + n_base + np*16 + b_n_sel)*2;
            asm volatile("ldmatrix.sync.aligned.m8n8.x4.trans.shared.b16 {%0,%1,%2,%3}, [%4];"
                : "=r"(r0), "=r"(r1), "=r"(r2), "=r"(r3) : "r"(addr));
            bf[2*np  ][0] = r0; bf[2*np  ][1] = r1;
            bf[2*np+1][0] = r2; bf[2*np+1][1] = r3;
        }
        #pragma unroll
        for (int nt = 0; nt < 8; nt++)
            asm volatile(
                "mma.sync.aligned.m16n8k16.row.col.f32.bf16.bf16.f32 "
                "{%0,%1,%2,%3}, {%4,%5,%6,%7}, {%8,%9}, {%0,%1,%2,%3};"
                : "+f"(acc[nt][0]), "+f"(acc[nt][1]), "+f"(acc[nt][2]), "+f"(acc[nt][3])
                : "r"(af[0]), "r"(af[1]), "r"(af[2]), "r"(af[3]),
                  "r"(bf[nt][0]), "r"(bf[nt][1]));
    }
}

#define KP 136

// ---------------------------------------------------------------------------
// Fused Q + KV projection, fully staged (K=128).
// cb 0 -> Q (scaled by HD^-0.5 * log2e, bf16), cb 1 -> K (bf16), cb 2 -> V (f16)
// ---------------------------------------------------------------------------
__global__ __launch_bounds__(256)
void qkv_k128(const bf16* __restrict__ qn, const bf16* __restrict__ kvn,
              const float* __restrict__ bq, const float* __restrict__ bkv,
              bf16* __restrict__ qout, bf16* __restrict__ kvout)
{
    extern __shared__ bf16 sm[];
    bf16* As = sm;
    bf16* Bs = sm + 64*KP;

    const int cb = blockIdx.x;
    const bool isQ = (cb == 0);
    const bf16*  A    = isQ ? qn : kvn;
    const bf16*  Wb   = isQ ? g_wq : g_wkv;
    const float* bias = isQ ? bq : bkv;
    bf16*        Cb   = isQ ? qout : kvout;
    const int N  = isQ ? Cc : 2*Cc;
    const int bn = isQ ? 0 : (cb - 1) * 128;

    const int tid  = threadIdx.x;
    const int bm   = blockIdx.y * 64;
    const int warp = tid >> 5;
    const int lane = tid & 31;
    const int g    = lane >> 2;
    const int t    = lane & 3;
    const int m_base = (warp >> 1) * 16;
    const int n_base = (warp & 1) * 64;

    {
        const unsigned aS = s2u(As);
        #pragma unroll
        for (int i = 0; i < 4; i++) {
            int id = tid + i*256;
            int r = id >> 4, c = id & 15;
            CP_ASYNC16(aS + (r*KP + c*8)*2, A + (size_t)(bm + r)*Cc + c*8);
        }
        const unsigned bS = s2u(Bs);
        #pragma unroll
        for (int i = 0; i < 8; i++) {
            int id = tid + i*256;
            int r = id >> 4, c = id & 15;
            CP_ASYNC16(bS + (r*KP + c*8)*2, Wb + (size_t)r*N + bn + c*8);
        }
        asm volatile("cp.async.commit_group;");
    }

    float acc[8][4];
    #pragma unroll
    for (int nt = 0; nt < 8; nt++)
        #pragma unroll
        for (int e = 0; e < 4; e++) acc[nt][e] = 0.0f;

    asm volatile("cp.async.wait_group 0;");
    __syncthreads();

    const unsigned aS = s2u(As);
    const unsigned bS = s2u(Bs);
    #pragma unroll
    for (int kt = 0; kt < 4; kt++)
        gemm_tile(aS + kt*32*2, bS + (kt*32*KP)*2, m_base, n_base, lane, acc, KP, KP);

    const float scale = 0.17677669529663689f * LOG2E;
    int row0 = bm + m_base + g;
    int row1 = row0 + 8;
    #pragma unroll
    for (int nt = 0; nt < 8; nt++) {
        int col = bn + n_base + nt*8 + 2*t;
        float b0 = bias[col], b1 = bias[col+1];
        float v00 = acc[nt][0] + b0;
        float v01 = acc[nt][1] + b1;
        float v10 = acc[nt][2] + b0;
        float v11 = acc[nt][3] + b1;
        if (isQ) { v00 *= scale; v01 *= scale; v10 *= scale; v11 *= scale; }
        if (cb == 2) {
            __half2 p0 = __floats2half2_rn(v00, v01);
            __half2 p1 = __floats2half2_rn(v10, v11);
            *(unsigned*)&Cb[(size_t)row0*N + col] = *(unsigned*)&p0;
            *(unsigned*)&Cb[(size_t)row1*N + col] = *(unsigned*)&p1;
        } else {
            bf162 p0 = __float22bfloat162_rn(make_float2(v00, v01));
            bf162 p1 = __float22bfloat162_rn(make_float2(v10, v11));
            *(unsigned*)&Cb[(size_t)row0*N + col] = *(unsigned*)&p0;
            *(unsigned*)&Cb[(size_t)row1*N + col] = *(unsigned*)&p1;
        }
    }
}

// ---------------------------------------------------------------------------
// Mega-fused tail: out = x + gelu(LN3(x) @ W1 + bm1) @ W2 + bm2,
// where x = attn @ Wp + bp + key_value is computed in-kernel and parked in
// fp32 smem (never hits HBM). One 64-row CTA per block.
// smem: As 64x136 + Hc 64x136 + 2x(128x136) bf16 + xsm 64x132 fp32 + part.
// ---------------------------------------------------------------------------
__global__ __launch_bounds__(256)
void tail_fused(const bf16* __restrict__ attn,
                const float* __restrict__ bp,
                const float* __restrict__ key_value,
                const float* __restrict__ lng,
                const float* __restrict__ lnb,
                const float* __restrict__ bm1,
                const float* __restrict__ bm2,
                float* __restrict__ out)
{
    extern __shared__ bf16 sm[];
    bf16*  As  = sm;                         // [64][136]  LN3 output
    bf16*  Hc  = sm + 64*KP;                 // [64][136]  attn tile, then gelu hidden
    bf16*  Wb0 = sm + 128*KP;                // [128][136]
    bf16*  Wb1 = sm + 256*KP;                // [128][136]
    float* xsm = (float*)(sm + 384*KP);      // [64][132]  fp32 x
    float* part = xsm + 64*132;              // [64][2] float2

    const int tid  = threadIdx.x;
    const int bm   = blockIdx.x * 64;
    const int warp = tid >> 5;
    const int lane = tid & 31;
    const int g    = lane >> 2;
    const int t    = lane & 3;
    const int m_base = (warp >> 1) * 16;
    const int warpN  = warp & 1;
    const int n_base = warpN * 64;

    const unsigned aS  = s2u(As);
    const unsigned hS  = s2u(Hc);
    const unsigned wS0 = s2u(Wb0);
    const unsigned wS1 = s2u(Wb1);

    // stage attn tile -> Hc, Wp -> Wb0
    #pragma unroll
    for (int i = 0; i < 4; i++) {
        int id = tid + i*256;
        int r = id >> 4, c = id & 15;
        CP_ASYNC16(hS + (r*KP + c*8)*2, attn + (size_t)(bm + r)*Cc + c*8);
    }
    #pragma unroll
    for (int i = 0; i < 8; i++) {
        int id = tid + i*256;
        int r = id >> 4, c = id & 15;
        CP_ASYNC16(wS0 + (r*KP + c*8)*2, g_wp + (size_t)r*Cc + c*8);
    }
    asm volatile("cp.async.commit_group;");
    asm volatile("cp.async.wait_group 0;");
    __syncthreads();

    // proj GEMM: x' = attn @ Wp
    float accP[8][4];
    #pragma unroll
    for (int nt = 0; nt < 8; nt++)
        #pragma unroll
        for (int e = 0; e < 4; e++) accP[nt][e] = 0.0f;
    #pragma unroll
    for (int kt = 0; kt < 4; kt++)
        gemm_tile(hS + kt*32*2, wS0 + (kt*32*KP)*2, m_base, n_base, lane, accP, KP, KP);

    // prefetch W1 chunk0 -> Wb1 (overlaps the epilogue/LN below)
    #pragma unroll
    for (int i = 0; i < 8; i++) {
        int id = tid + i*256;
        int r = id >> 4, c = id & 15;
        CP_ASYNC16(wS1 + (r*KP + c*8)*2, g_w1 + (size_t)r*MLPD + c*8);
    }
    asm volatile("cp.async.commit_group;");

    // epilogue: x = x' + bp + key_value -> xsm, accumulate LN sums
    const int lr0 = m_base + g, lr1 = lr0 + 8;
    const int row0g = bm + lr0, row1g = bm + lr1;
    float s0 = 0.f, q0 = 0.f, s1 = 0.f, q1 = 0.f;
    #pragma unroll
    for (int nt = 0; nt < 8; nt++) {
        int lc = n_base + nt*8 + 2*t;
        float b0 = bp[lc], b1 = bp[lc+1];
        float2 r0 = *(const float2*)&key_value[(size_t)row0g*Cc + lc];
        float2 r1 = *(const float2*)&key_value[(size_t)row1g*Cc + lc];
        float v00 = accP[nt][0] + b0 + r0.x;
        float v01 = accP[nt][1] + b1 + r0.y;
        float v10 = accP[nt][2] + b0 + r1.x;
        float v11 = accP[nt][3] + b1 + r1.y;
        xsm[lr0*132 + lc] = v00; xsm[lr0*132 + lc + 1] = v01;
        xsm[lr1*132 + lc] = v10; xsm[lr1*132 + lc + 1] = v11;
        s0 += v00 + v01;  q0 += v00*v00 + v01*v01;
        s1 += v10 + v11;  q1 += v10*v10 + v11*v11;
    }
    #pragma unroll
    for (int off = 1; off < 4; off <<= 1) {
        s0 += __shfl_xor_sync(0xffffffff, s0, off);
        q0 += __shfl_xor_sync(0xffffffff, q0, off);
        s1 += __shfl_xor_sync(0xffffffff, s1, off);
        q1 += __shfl_xor_sync(0xffffffff, q1, off);
    }
    if (t == 0) {
        *(float2*)&part[(lr0*2 + warpN)*2] = make_float2(s0, q0);
        *(float2*)&part[(lr1*2 + warpN)*2] = make_float2(s1, q1);
    }
    __syncthreads();

    // LN3 normalize xsm -> As (bf16)
    {
        float2 a0 = *(float2*)&part[(lr0*2 + 0)*2];
        float2 a1 = *(float2*)&part[(lr0*2 + 1)*2];
        float2 c0 = *(float2*)&part[(lr1*2 + 0)*2];
        float2 c1 = *(float2*)&part[(lr1*2 + 1)*2];
        float m0 = (a0.x + a1.x) * (1.0f/Cc);
        float v0 = (a0.y + a1.y) * (1.0f/Cc) - m0*m0;
        float i0 = rsqrtf(v0 + 1e-5f);
        float m1 = (c0.x + c1.x) * (1.0f/Cc);
        float v1 = (c0.y + c1.y) * (1.0f/Cc) - m1*m1;
        float i1 = rsqrtf(v1 + 1e-5f);
        #pragma unroll
        for (int nt = 0; nt < 8; nt++) {
            int lc = n_base + nt*8 + 2*t;
            float gg0 = lng[lc], gg1b = lng[lc+1];
            float bb0 = lnb[lc], bb1 = lnb[lc+1];
            float x00 = xsm[lr0*132 + lc], x01 = xsm[lr0*132 + lc + 1];
            float x10 = xsm[lr1*132 + lc], x11 = xsm[lr1*132 + lc + 1];
            bf162 p0 = __float22bfloat162_rn(make_float2((x00-m0)*i0*gg0 + bb0,
                                                         (x01-m0)*i0*gg1b + bb1));
            bf162 p1 = __float22bfloat162_rn(make_float2((x10-m1)*i1*gg0 + bb0,
                                                         (x11-m1)*i1*gg1b + bb1));
            *(unsigned*)&As[lr0*KP + lc] = *(unsigned*)&p0;
            *(unsigned*)&As[lr1*KP + lc] = *(unsigned*)&p1;
        }
    }
    asm volatile("cp.async.wait_group 0;");   // W1 chunk0 landed in Wb1
    __syncthreads();

    // MLP streaming loop: step even = W1 chunk (buffer Wb1), odd = W2 (Wb0)
    float accB[8][4];
    #pragma unroll
    for (int nt = 0; nt < 8; nt++)
        #pragma unroll
        for (int e = 0; e < 4; e++) accB[nt][e] = 0.0f;

    #pragma unroll
    for (int step = 0; step < 8; step++) {
        const int nxt = step + 1;
        if (nxt < 8) {
            const int cc = nxt >> 1;
            const unsigned dst = (nxt & 1) ? wS0 : wS1;
            if ((nxt & 1) == 0) {
                #pragma unroll
                for (int i = 0; i < 8; i++) {
                    int id = tid + i*256;
                    int r = id >> 4, c = id & 15;
                    CP_ASYNC16(dst + (r*KP + c*8)*2,
                               g_w1 + (size_t)r*MLPD + cc*128 + c*8);
                }
            } else {
                #pragma unroll
                for (int i = 0; i < 8; i++) {
                    int id = tid + i*256;
                    int r = id >> 4, c = id & 15;
                    CP_ASYNC16(dst + (r*KP + c*8)*2,
                               g_w2 + (size_t)(cc*128 + r)*Cc + c*8);
                }
            }
            asm volatile("cp.async.commit_group;");
            asm volatile("cp.async.wait_group 1;");
        } else {
            asm volatile("cp.async.wait_group 0;");
        }
        __syncthreads();

        const unsigned wS = (step & 1) ? wS0 : wS1;
        if ((step & 1) == 0) {
            const int cc = step >> 1;
            float accA[8][4];
            #pragma unroll
            for (int nt = 0; nt < 8; nt++)
                #pragma unroll
                for (int e = 0; e < 4; e++) accA[nt][e] = 0.0f;
            #pragma unroll
            for (int kt = 0; kt < 4; kt++)
                gemm_tile(aS + kt*32*2, wS + (kt*32*KP)*2, m_base, n_base, lane,
                          accA, KP, KP);

            #pragma unroll
            for (int nt = 0; nt < 8; nt++) {
                int lc  = n_base + nt*8 + 2*t;
                int col = cc*128 + lc;
                float b0 = bm1[col], b1 = bm1[col+1];
                float v00 = accA[nt][0] + b0;
                float v01 = accA[nt][1] + b1;
                float v10 = accA[nt][2] + b0;
                float v11 = accA[nt][3] + b1;
                v00 = 0.5f*v00*(1.0f + erff(v00*0.70710678118654752f));
                v01 = 0.5f*v01*(1.0f + erff(v01*0.70710678118654752f));
                v10 = 0.5f*v10*(1.0f + erff(v10*0.70710678118654752f));
                v11 = 0.5f*v11*(1.0f + erff(v11*0.70710678118654752f));
                bf162 p0 = __float22bfloat162_rn(make_float2(v00, v01));
                bf162 p1 = __float22bfloat162_rn(make_float2(v10, v11));
                *(unsigned*)&Hc[lr0*KP + lc] = *(unsigned*)&p0;
                *(unsigned*)&Hc[lr1*KP + lc] = *(unsigned*)&p1;
            }
            __syncthreads();
        } else {
            #pragma unroll
            for (int kt = 0; kt < 4; kt++)
                gemm_tile(hS + kt*32*2, wS + (kt*32*KP)*2, m_base, n_base, lane,
                          accB, KP, KP);
            __syncthreads();
        }
    }

    // final epilogue: out = accB + bm2 + x (from smem)
    #pragma unroll
    for (int nt = 0; nt < 8; nt++) {
        int lc = n_base + nt*8 + 2*t;
        float b0 = bm2[lc], b1 = bm2[lc+1];
        float x00 = xsm[lr0*132 + lc], x01 = xsm[lr0*132 + lc + 1];
        float x10 = xsm[lr1*132 + lc], x11 = xsm[lr1*132 + lc + 1];
        *(float2*)&out[(size_t)row0g*Cc + lc] =
            make_float2(accB[nt][0] + b0 + x00, accB[nt][1] + b1 + x01);
        *(float2*)&out[(size_t)row1g*Cc + lc] =
            make_float2(accB[nt][2] + b0 + x10, accB[nt][3] + b1 + x11);
    }
}

// ---------------------------------------------------------------------------
// Neighborhood attention v6 (unchanged).
// ---------------------------------------------------------------------------
#define PR 14
#define PC 10
#define PTOK 140
#define NPAD 160
#define KSP 40
#define PP  168
#define QP  40

__global__ __launch_bounds__(256)
void nat_attn6(const bf16* __restrict__ q,
               const bf16* __restrict__ kv,
               const float* __restrict__ rpb,
               bf16* __restrict__ out)
{
    extern __shared__ char smc[];
    bf16*   Ks = (bf16*)smc;
    __half* Vs = (__half*)(Ks + NPAD*KSP);
    __half* Ps = (__half*)(Vs + NPAD*KSP);
    bf16*   Qs = (bf16*)(Ps + 32*PP);
    float*  rs   = (float*)(Qs + 32*QP);
    float*  part = rs + 169;

    const int blk = blockIdx.x;
    const int h   = blk & 3;
    const int r2  = blk >> 2;
    const int b   = r2 >> 7;
    const int rem = r2 & 127;
    const int it  = (rem >> 4) << 3;
    const int jt  = (rem & 15) << 2;

    int ip0 = it - 3; if (ip0 < 0) ip0 = 0; if (ip0 > Hh - PR) ip0 = Hh - PR;
    int jp0 = jt - 3; if (jp0 < 0) jp0 = 0; if (jp0 > Ww - PC) jp0 = Ww - PC;

    const int tid  = threadIdx.x;
    const int base = b * (Hh*Ww);
    const uint4* kv4 = (const uint4*)kv;

    for (int f = tid; f < PTOK*8; f += 256) {
        int tok = f >> 3;
        int c   = f & 7;
        int r   = (tok*205) >> 11;
        int cc  = tok - r*PC;
        int g   = base + (ip0 + r)*Ww + (jp0 + cc);
        if (c < 4) {
            *(uint4*)&Ks[tok*KSP + c*8] = kv4[(size_t)g*32 + h*4 + c];
        } else {
            int c2 = c - 4;
            *(uint4*)&Vs[tok*KSP + c2*8] = kv4[(size_t)g*32 + 16 + h*4 + c2];
        }
    }
    for (int f = tid; f < 100; f += 256) {
        int row = PTOK + f/5, cc = (f - (f/5)*5)*8;
        uint4 z = make_uint4(0,0,0,0);
        *(uint4*)&Vs[row*KSP + cc] = z;
    }
    for (int f = tid; f < 128; f += 256) {
        int qq = f >> 2, c = f & 3;
        int qi = qq >> 2, qj = qq & 3;
        int g = base + (it + qi)*Ww + (jt + qj);
        *(uint4*)&Qs[qq*QP + c*8] = ((const uint4*)q)[(size_t)g*16 + h*4 + c];
    }
    for (int f = tid; f < 169; f += 256) rs[f] = rpb[h*169 + f] * LOG2E;
    __syncthreads();

    const int w    = tid >> 5;
    const int lane = tid & 31;
    const int a_row = lane & 15;
    const int a_k   = (lane >> 4) << 3;
    const int bn_row = (lane & 7) + ((lane >> 4) << 3);
    const int bk_col = ((lane >> 3) & 1) << 3;
    const int b_k   = (lane & 7) + (((lane >> 3) & 1) << 3);

    const int m_base = (w >> 2) * 16;
    const int warpN  = w & 3;
    const int n_base = warpN * 40;

    float acc[5][4];
    {
        const unsigned qS = s2u(Qs), kS = s2u(Ks);
        #pragma unroll
        for (int nt = 0; nt < 5; nt++)
            #pragma unroll
            for (int e = 0; e < 4; e++) acc[nt][e] = 0.0f;

        #pragma unroll
        for (int kk = 0; kk < 32; kk += 16) {
            unsigned af[4], bf[5][2];
            unsigned addr = qS + ((m_base + a_row)*QP + kk + a_k)*2;
            asm volatile("ldmatrix.sync.aligned.m8n8.x4.shared.b16 {%0,%1,%2,%3}, [%4];"
                : "=r"(af[0]), "=r"(af[1]), "=r"(af[2]), "=r"(af[3]) : "r"(addr));
            #pragma unroll
            for (int np = 0; np < 2; np++) {
                unsigned r0, r1, r2, r3;
                addr = kS + ((n_base + np*16 + bn_row)*KSP + kk + bk_col)*2;
                asm volatile("ldmatrix.sync.aligned.m8n8.x4.shared.b16 {%0,%1,%2,%3}, [%4];"
                    : "=r"(r0), "=r"(r1), "=r"(r2), "=r"(r3) : "r"(addr));
                bf[2*np][0] = r0; bf[2*np][1] = r1;
                bf[2*np+1][0] = r2; bf[2*np+1][1] = r3;
            }
            {
                unsigned r0, r1;
                addr = kS + ((n_base + 32 + (lane & 7))*KSP + kk + bk_col)*2;
                asm volatile("ldmatrix.sync.aligned.m8n8.x2.shared.b16 {%0,%1}, [%2];"
                    : "=r"(r0), "=r"(r1) : "r"(addr));
                bf[4][0] = r0; bf[4][1] = r1;
            }
            #pragma unroll
            for (int nt = 0; nt < 5; nt++)
                asm volatile(
                    "mma.sync.aligned.m16n8k16.row.col.f32.bf16.bf16.f32 "
                    "{%0,%1,%2,%3}, {%4,%5,%6,%7}, {%8,%9}, {%0,%1,%2,%3};"
                    : "+f"(acc[nt][0]), "+f"(acc[nt][1]), "+f"(acc[nt][2]), "+f"(acc[nt][3])
                    : "r"(af[0]), "r"(af[1]), "r"(af[2]), "r"(af[3]),
                      "r"(bf[nt][0]), "r"(bf[nt][1]));
        }
    }

    {
        const int row0 = m_base + (lane >> 2);
        const int row1 = row0 + 8;

        int io0, jo0, bi0, bj0, io1, jo1, bi1, bj1;
        {
            int qi = row0 >> 2, qj = row0 & 3;
            int gi = it + qi, gj = jt + qj;
            int i0 = gi - 3; if (i0 < 0) i0 = 0; if (i0 > Hh - Kk) i0 = Hh - Kk;
            int j0 = gj - 3; if (j0 < 0) j0 = 0; if (j0 > Ww - Kk) j0 = Ww - Kk;
            io0 = i0 - ip0; jo0 = j0 - jp0;
            bi0 = ip0 - gi + (Kk - 1); bj0 = jp0 - gj + (Kk - 1);
        }
        {
            int qi = row1 >> 2, qj = row1 & 3;
            int gi = it + qi, gj = jt + qj;
            int i0 = gi - 3; if (i0 < 0) i0 = 0; if (i0 > Hh - Kk) i0 = Hh - Kk;
            int j0 = gj - 3; if (j0 < 0) j0 = 0; if (j0 > Ww - Kk) j0 = Ww - Kk;
            io1 = i0 - ip0; jo1 = j0 - jp0;
            bi1 = ip0 - gi + (Kk - 1); bj1 = jp0 - gj + (Kk - 1);
        }

        float s0 = 0.f, s1 = 0.f;
        #pragma unroll
        for (int nt = 0; nt < 5; nt++) {
            int colA = n_base + nt*8 + 2*(lane & 3);
            int tA = colA, tB = colA + 1;
            int rA = (tA*205) >> 11, cA = tA - rA*PC;
            int rB = (tB*205) >> 11, cB = tB - rB*PC;
            bool inA = (tA < PTOK), inB = (tB < PTOK);

            {
                bool vA = inA && (unsigned)(rA - io0) < 7u && (unsigned)(cA - jo0) < 7u;
                bool vB = inB && (unsigned)(rB - io0) < 7u && (unsigned)(cB - jo0) < 7u;
                unsigned pk = 0u;
                if (vA | vB) {
                    float y0 = vA ? acc[nt][0] + rs[(bi0 + rA)*13 + bj0 + cA] : -88.f;
                    float y1 = vB ? acc[nt][1] + rs[(bi0 + rB)*13 + bj0 + cB] : -88.f;
                    __half2 e2 = h2exp2(__floats2half2_rn(y0, y1));
                    pk = *(unsigned*)&e2;
                    float2 f = __half22float2(e2);
                    s0 += f.x + f.y;
                }
                *(unsigned*)&Ps[row0*PP + colA] = pk;
            }
            {
                bool vA = inA && (unsigned)(rA - io1) < 7u && (unsigned)(cA - jo1) < 7u;
                bool vB = inB && (unsigned)(rB - io1) < 7u && (unsigned)(cB - jo1) < 7u;
                unsigned pk = 0u;
                if (vA | vB) {
                    float y0 = vA ? acc[nt][2] + rs[(bi1 + rA)*13 + bj1 + cA] : -88.f;
                    float y1 = vB ? acc[nt][3] + rs[(bi1 + rB)*13 + bj1 + cB] : -88.f;
                    __half2 e2 = h2exp2(__floats2half2_rn(y0, y1));
                    pk = *(unsigned*)&e2;
                    float2 f = __half22float2(e2);
                    s1 += f.x + f.y;
                }
                *(unsigned*)&Ps[row1*PP + colA] = pk;
            }
        }
        #pragma unroll
        for (int off = 1; off < 4; off <<= 1) {
            s0 += __shfl_xor_sync(0xffffffff, s0, off);
            s1 += __shfl_xor_sync(0xffffffff, s1, off);
        }
        if ((lane & 3) == 0) {
            part[row0*4 + warpN] = s0;
            part[row1*4 + warpN] = s1;
        }
    }
    __syncthreads();

    {
        const int n_base2 = warpN * 8;
        const unsigned pS = s2u(Ps), vS = s2u(Vs);
        float acc2[4] = {0.f, 0.f, 0.f, 0.f};

        #pragma unroll
        for (int kt = 0; kt < 10; kt++) {
            int kk = kt*16;
            unsigned af[4];
            unsigned addr = pS + ((m_base + a_row)*PP + kk + a_k)*2;
            asm volatile("ldmatrix.sync.aligned.m8n8.x4.shared.b16 {%0,%1,%2,%3}, [%4];"
                : "=r"(af[0]), "=r"(af[1]), "=r"(af[2]), "=r"(af[3]) : "r"(addr));
            unsigned b0, b1;
            addr = vS + ((kk + b_k)*KSP + n_base2)*2;
            asm volatile("ldmatrix.sync.aligned.m8n8.x2.trans.shared.b16 {%0,%1}, [%2];"
                : "=r"(b0), "=r"(b1) : "r"(addr));
            asm volatile(
                "mma.sync.aligned.m16n8k16.row.col.f32.f16.f16.f32 "
                "{%0,%1,%2,%3}, {%4,%5,%6,%7}, {%8,%9}, {%0,%1,%2,%3};"
                : "+f"(acc2[0]), "+f"(acc2[1]), "+f"(acc2[2]), "+f"(acc2[3])
                : "r"(af[0]), "r"(af[1]), "r"(af[2]), "r"(af[3]),
                  "r"(b0), "r"(b1));
        }

        const int col = n_base2 + 2*(lane & 3);
        #pragma unroll
        for (int half = 0; half < 2; half++) {
            int qq = m_base + (lane >> 2) + half*8;
            float rinv = 1.0f / (part[qq*4+0] + part[qq*4+1] + part[qq*4+2] + part[qq*4+3]);
            int qi = qq >> 2, qj = qq & 3;
            int g = base + (it + qi)*Ww + (jt + qj);
            bf162 p = __float22bfloat162_rn(make_float2(acc2[half*2] * rinv,
                                                        acc2[half*2+1] * rinv));
            *(unsigned*)&out[(size_t)g*Cc + h*32 + col] = *(unsigned*)&p;
        }
    }
}

// ---------------------------------------------------------------------------
// Launch
// ---------------------------------------------------------------------------
extern "C" void kernel_launch(void* const* d_in, const int* in_sizes, int n_in,
                              void* d_out, int out_size)
{
    const float* query     = (const float*)d_in[0];
    const float* key_value = (const float*)d_in[1];
    const float* g1  = (const float*)d_in[2];
    const float* b1  = (const float*)d_in[3];
    const float* g2  = (const float*)d_in[4];
    const float* b2  = (const float*)d_in[5];
    const float* g3  = (const float*)d_in[6];
    const float* b3  = (const float*)d_in[7];
    const float* Wq  = (const float*)d_in[8];
    const float* bq  = (const float*)d_in[9];
    const float* Wkv = (const float*)d_in[10];
    const float* bkv = (const float*)d_in[11];
    const float* Wp  = (const float*)d_in[12];
    const float* bp  = (const float*)d_in[13];
    const float* rpb = (const float*)d_in[14];
    const float* W1  = (const float*)d_in[15];
    const float* bm1 = (const float*)d_in[16];
    const float* W2  = (const float*)d_in[17];
    const float* bm2 = (const float*)d_in[18];
    float* out = (float*)d_out;

    bf16*  qn     = nullptr; cudaGetSymbolAddress((void**)&qn,     g_qn);
    bf16*  kvn    = nullptr; cudaGetSymbolAddress((void**)&kvn,    g_kvn);
    bf16*  qbuf   = nullptr; cudaGetSymbolAddress((void**)&qbuf,   g_q);
    bf16*  kvbuf  = nullptr; cudaGetSymbolAddress((void**)&kvbuf,  g_kv);
    bf16*  attn   = nullptr; cudaGetSymbolAddress((void**)&attn,   g_attn);

    const int k128_smem = (64 + 128) * KP * 2;   // 52224 B
    const int attn_smem = (2*NPAD*KSP + 32*PP + 32*QP) * 2 + (169 + 128) * 4;
    const int tail_smem = 384*KP*2 + 64*132*4 + 64*4*4;   // 139264 B

    static bool attr_set = false;
    if (!attr_set) {
        cudaFuncSetAttribute(qkv_k128,
                             cudaFuncAttributeMaxDynamicSharedMemorySize, k128_smem);
        cudaFuncSetAttribute(nat_attn6,
                             cudaFuncAttributeMaxDynamicSharedMemorySize, attn_smem);
        cudaFuncSetAttribute(tail_fused,
                             cudaFuncAttributeMaxDynamicSharedMemorySize, tail_smem);
        attr_set = true;
    }

    // 1) LN1 + LN2 + weight conversion in ONE launch
    prep_kernel<<<4288, 256>>>(query, g1, b1, qn, key_value, g2, b2, kvn,
                               Wq, Wkv, Wp, W1, W2);

    // 2) Fused Q + KV projections (Q pre-scaled with log2e; V written as f16)
    qkv_k128<<<dim3(3, NTOK/64), 256, k128_smem>>>(qn, kvn, bq, bkv, qbuf, kvbuf);

    // 3) Neighborhood attention (tensor-core, paired f16 exp2)
    nat_attn6<<<Bq*(Hh/8)*(Ww/4)*NHh, 256, attn_smem>>>(qbuf, kvbuf, rpb, attn);

    // 4) Mega-fused tail: proj + residual + LN3 + MLP + final residual
    tail_fused<<<NTOK/64, 256, tail_smem>>>(attn, bp, key_value, g3, b3,
                                            bm1, bm2, out);
}